// round 14
// baseline (speedup 1.0000x reference)
#include <cuda_runtime.h>
#include <math.h>
#include <float.h>

constexpr int NMAX = 10000;
constexpr int EMAX = 50000;
constexpr int D    = 32;
constexpr int H    = 4;
constexpr int GRID = 444;   // <= 148 SMs * 3 blocks even in worst residency;
                            // launch_bounds(256,4) targets 4/SM = 592 capacity

// Scratch (no allocations allowed -> __device__ globals).
// INVARIANTS per launch:
//   g_denom : zeroed by a cudaMemsetAsync graph node before k_all
//   g_agg   : zero at entry; read-then-zeroed by its sole reader (node warp)
//   g_ex    : fully overwritten each launch
//   g_arrive/g_depart : return to 0 via the two-counter barrier reset
__device__ float g_denom[NMAX * H];
__device__ float g_agg  [NMAX * D];
__device__ float g_ex   [EMAX * H];
__device__ int   g_arrive;
__device__ int   g_depart;

__device__ __forceinline__ float warpSum32(float x) {
    #pragma unroll
    for (int off = 16; off; off >>= 1)
        x += __shfl_xor_sync(0xffffffffu, x, off);
    return x;
}

__device__ __forceinline__ float dot4(float4 a, float4 b) {
    return a.x*b.x + a.y*b.y + a.z*b.z + a.w*b.w;
}

// ---------------------------------------------------------------------------
// Single persistent kernel:
//  phase 1: edge tiles (warp-per-edge hypernetwork GEMVs + logits + fused
//           exp/denom/agg atomics)  [verified-best body]
//  barrier: threadfence + arrive counter; blocks PRELOAD their first node
//           tile's node_w rows while other blocks finish phase 1 (overlap)
//  phase 2: node tiles (GEMV+relu+residual+LN, restores g_agg) and attn
//           tiles (one thread per edge, float4)
// ---------------------------------------------------------------------------
__global__ void __launch_bounds__(256, 4) k_all(
    const float* __restrict__ in_feat,
    const int*   __restrict__ src,
    const int*   __restrict__ dst,
    const float* __restrict__ skw,
    const float* __restrict__ dkw,
    const float* __restrict__ skb,
    const float* __restrict__ dkb,
    const float* __restrict__ svw,
    const float* __restrict__ dvw,
    const float* __restrict__ svb,
    const float* __restrict__ dvb,
    const float* __restrict__ query,
    const float* __restrict__ node_w,
    const float* __restrict__ node_b,
    const float* __restrict__ ln_w,
    const float* __restrict__ ln_b,
    float* __restrict__ out,
    float* __restrict__ key_out,
    float* __restrict__ val_out,
    float* __restrict__ attn_out,
    int E, int N)
{
    const int lane = threadIdx.x & 31;
    const int wl   = threadIdx.x >> 5;
    const int c    = lane & 7;
    __shared__ float kbuf[8][32];
    __shared__ float vbuf[8][32];
    __shared__ __align__(16) float sa[8][D];
    __shared__ float obuf[8][32];

    const int edgeTiles = (E + 7) / 8;
    const int nodeTiles = (N + 7) / 8;
    const int attnTiles = (E + 255) / 256;
    const float4* inf4 = (const float4*)in_feat;

    // ===================== phase 1: edges =====================
    for (int t = blockIdx.x; t < edgeTiles; t += GRID) {
        const int e = t * 8 + wl;
        if (e < E) {
            const int s = src[e];
            const int d = dst[e];
            const float4 u4 = inf4[(long)s * 8 + c];
            const float4 v4 = inf4[(long)d * 8 + c];

            const float4* A  = (const float4*)skw + (long)e * 256;
            const float4* B  = (const float4*)dkw + (long)e * 256;
            const float4* Cw = (const float4*)svw + (long)e * 256;
            const float4* Dw = (const float4*)dvw + (long)e * 256;

            #pragma unroll
            for (int i = 0; i < 8; i++) {
                const int idx = i * 32 + lane;
                float4 a  = __ldcs(A  + idx);
                float4 b  = __ldcs(B  + idx);
                float4 cc = __ldcs(Cw + idx);
                float4 dd = __ldcs(Dw + idx);
                float pk = dot4(a, u4) + dot4(b, v4);
                float pv = dot4(cc, u4) + dot4(dd, v4);
                pk += __shfl_xor_sync(0xffffffffu, pk, 1);
                pv += __shfl_xor_sync(0xffffffffu, pv, 1);
                pk += __shfl_xor_sync(0xffffffffu, pk, 2);
                pv += __shfl_xor_sync(0xffffffffu, pv, 2);
                pk += __shfl_xor_sync(0xffffffffu, pk, 4);
                pv += __shfl_xor_sync(0xffffffffu, pv, 4);
                if (c == 0) {
                    const int row = i * 4 + (lane >> 3);
                    kbuf[wl][row] = pk;
                    vbuf[wl][row] = pv;
                }
            }
            __syncwarp();

            const long eo = (long)e * 32 + lane;
            float kacc = kbuf[wl][lane] + __ldcs(skb + eo) + __ldcs(dkb + eo);
            float vacc = vbuf[wl][lane] + __ldcs(svb + eo) + __ldcs(dvb + eo);
            key_out[eo] = kacc;
            val_out[eo] = vacc;

            float p = kacc * query[(long)d * D + lane];
            p += __shfl_xor_sync(0xffffffffu, p, 1);
            p += __shfl_xor_sync(0xffffffffu, p, 2);
            p += __shfl_xor_sync(0xffffffffu, p, 4);

            const float ex = expf(p);
            atomicAdd(&g_agg[d * D + lane], vacc * ex);
            if (c == 0) {
                const int h = lane >> 3;
                g_ex[e * H + h] = ex;
                atomicAdd(&g_denom[d * H + h], ex);
            }
        }
        __syncwarp();
    }

    // ===================== arrive =====================
    __threadfence();
    __syncthreads();
    if (threadIdx.x == 0) atomicAdd(&g_arrive, 1);

    // ======= preload first node tile (independent of edge results) =======
    float4 w[8];
    float nb = 0.f, infv = 0.f, lw = 0.f, lb = 0.f;
    const int t0 = blockIdx.x;               // first tail tile (node: t0<1250)
    const int n0 = t0 * 8 + wl;
    const bool havePre = (t0 < nodeTiles) && (n0 < N);
    if (havePre) {
        const float4* W = (const float4*)node_w + (long)n0 * 256 + lane;
        #pragma unroll
        for (int i = 0; i < 8; i++) w[i] = __ldcs(W + i * 32);
        nb   = node_b[(long)n0 * D + lane];
        infv = in_feat[(long)n0 * D + lane];
        lw   = ln_w[lane];
        lb   = ln_b[lane];
    }

    // ===================== spin until all blocks arrived =====================
    if (threadIdx.x == 0) {
        while (*(volatile int*)&g_arrive < GRID) { }
    }
    __syncthreads();

    // ===================== phase 2: tail =====================
    const int totalTail = nodeTiles + attnTiles;
    for (int t = blockIdx.x; t < totalTail; t += GRID) {
        if (t < nodeTiles) {
            const int n = t * 8 + wl;
            if (n < N) {
                if (t != t0) {   // not the preloaded tile: load now
                    const float4* W = (const float4*)node_w + (long)n * 256 + lane;
                    #pragma unroll
                    for (int i = 0; i < 8; i++) w[i] = __ldcs(W + i * 32);
                    nb   = node_b[(long)n * D + lane];
                    infv = in_feat[(long)n * D + lane];
                    lw   = ln_w[lane];
                    lb   = ln_b[lane];
                }
                const float den = g_denom[n * H + (lane >> 3)];
                const float agv = g_agg[n * D + lane];
                __syncwarp();
                g_agg[n * D + lane] = 0.0f;   // restore invariant

                float a = (den > 0.0f) ? (agv / den) : 0.0f;
                sa[wl][lane] = a;
                __syncwarp();

                const float4 x4 = ((const float4*)sa[wl])[c];
                #pragma unroll
                for (int i = 0; i < 8; i++) {
                    float p = dot4(w[i], x4);
                    p += __shfl_xor_sync(0xffffffffu, p, 1);
                    p += __shfl_xor_sync(0xffffffffu, p, 2);
                    p += __shfl_xor_sync(0xffffffffu, p, 4);
                    if (c == 0) obuf[wl][i * 4 + (lane >> 3)] = p;
                }
                __syncwarp();

                float acc = fmaxf(obuf[wl][lane] + nb, 0.0f);
                float x = infv + acc;
                float mu = warpSum32(x) * (1.0f / 32.0f);
                float xm = x - mu;
                float var = warpSum32(xm * xm) * (1.0f / 32.0f);
                float y = xm * rsqrtf(var + 1e-5f) * lw + lb;
                out[(long)n * D + lane] = y;
            }
        } else {
            const int e = (t - nodeTiles) * 256 + threadIdx.x;
            if (e < E) {
                const int d = dst[e];
                const float4 ex4 = ((const float4*)g_ex)[e];
                const float4 dn  = *(const float4*)(g_denom + d * H);
                float4 at;
                at.x = ex4.x / dn.x;
                at.y = ex4.y / dn.y;
                at.z = ex4.z / dn.z;
                at.w = ex4.w / dn.w;
                ((float4*)attn_out)[e] = at;
            }
        }
        __syncwarp();
    }

    // ===================== reset barrier counters =====================
    __syncthreads();
    if (threadIdx.x == 0) {
        // last departing block restores both counters to zero; every block
        // has already exited the spin, so no one reads g_arrive anymore.
        if (atomicAdd(&g_depart, 1) == GRID - 1) {
            g_arrive = 0;
            g_depart = 0;
            __threadfence();
        }
    }
}

// ---------------------------------------------------------------------------
extern "C" void kernel_launch(void* const* d_in, const int* in_sizes, int n_in,
                              void* d_out, int out_size) {
    const float* in_feat = (const float*)d_in[0];
    const int*   src     = (const int*)  d_in[1];
    const int*   dst     = (const int*)  d_in[2];
    const float* skw     = (const float*)d_in[3];
    const float* dkw     = (const float*)d_in[4];
    const float* skb     = (const float*)d_in[5];
    const float* dkb     = (const float*)d_in[6];
    const float* svw     = (const float*)d_in[7];
    const float* dvw     = (const float*)d_in[8];
    const float* svb     = (const float*)d_in[9];
    const float* dvb     = (const float*)d_in[10];
    const float* query   = (const float*)d_in[11];
    const float* node_w  = (const float*)d_in[12];
    const float* node_b  = (const float*)d_in[13];
    const float* ln_w    = (const float*)d_in[14];
    const float* ln_b    = (const float*)d_in[15];

    const int N = in_sizes[0] / D;   // 10000
    const int E = in_sizes[1];       // 50000

    float* out_ptr  = (float*)d_out;
    float* key_ptr  = out_ptr + (long)N * D;
    float* val_ptr  = key_ptr + (long)E * D;
    float* attn_ptr = val_ptr + (long)E * D;

    // zero g_denom via a memset graph node
    void* denom_ptr = nullptr;
    cudaGetSymbolAddress(&denom_ptr, g_denom);
    cudaMemsetAsync(denom_ptr, 0, NMAX * H * sizeof(float));

    k_all<<<GRID, 256>>>(in_feat, src, dst, skw, dkw, skb, dkb,
                         svw, dvw, svb, dvb, query,
                         node_w, node_b, ln_w, ln_b,
                         out_ptr, key_ptr, val_ptr, attn_ptr, E, N);
}